// round 13
// baseline (speedup 1.0000x reference)
#include <cuda_runtime.h>
#include <cuda_bf16.h>
#include <cstdint>

// Problem constants
#define B_   8
#define C_   64
#define N_   4096
#define K_   20
#define M_   8
#define OUTC 64
#define CM   (C_ * M_)      // 512
#define P_   (B_ * N_)      // 32768 points
#define NEG_SLOPE 0.2f

#define PTS  64              // points per fused block
#define TPB  256

// Scratch (allocation-free: __device__ global)
__device__ float g_ft[(size_t)B_ * N_ * C_];        // feature transposed (B,N,C)  8 MB

// ---------------------------------------------------------------------------
// Kernel 1: transpose feature (B,C,N) -> ft (B,N,C)
// ---------------------------------------------------------------------------
__global__ void k_transpose(const float* __restrict__ feature) {
    __shared__ float tile[32][33];
    int b  = blockIdx.z;
    int c0 = blockIdx.y * 32;
    int n0 = blockIdx.x * 32;
    int tx = threadIdx.x;
    int ty = threadIdx.y;

    const float* src = feature + ((size_t)b * C_) * N_;
#pragma unroll
    for (int i = 0; i < 32; i += 8) {
        tile[ty + i][tx] = src[(size_t)(c0 + ty + i) * N_ + (n0 + tx)];
    }
    __syncthreads();
    float* dst = g_ft + ((size_t)b * N_) * C_;
#pragma unroll
    for (int i = 0; i < 32; i += 8) {
        dst[(size_t)(n0 + ty + i) * C_ + (c0 + tx)] = tile[tx][ty + i];
    }
}

// ---------------------------------------------------------------------------
// Fused kernel: perm + softmax + aggregation + GEMM + epilogue.
// One block = 64 points (all in one batch: 64 | 4096).  256 threads.
// Dynamic smem layout (floats):
//   sagg [64][513]   = 32832   (agg vectors, pad-513 -> conflict-free p-strided
//                               GEMM reads; scalar stores only — row base is
//                               NOT 16B-aligned for odd p)
//   perm [64][20*9]  = 11520   (logits then softmaxed weights, inner pad 9)
//   Ws   [32][65]    =  2080   (W k-chunk staging)
//   scen [64][4]     =   256   (center xyz per point)
//   skern[32]        =    32
//   sidx [64*20] int =  1280
// total 48000 words = 192000 B
// ---------------------------------------------------------------------------
#define SAGG_OFF  0
#define PERM_OFF  (SAGG_OFF + PTS * 513)            // 32832
#define WS_OFF    (PERM_OFF + PTS * 180)            // 44352
#define SCEN_OFF  (WS_OFF   + 32 * 65)              // 46432
#define SKERN_OFF (SCEN_OFF + PTS * 4)              // 46688
#define SIDX_OFF  (SKERN_OFF + 32)                  // 46720
#define SMEM_WORDS (SIDX_OFF + PTS * K_)            // 48000

__global__ __launch_bounds__(TPB) void k_fused(const float* __restrict__ x,
                                               const int* __restrict__ nbr,
                                               const float* __restrict__ kern,
                                               const float* __restrict__ w,
                                               const float* __restrict__ bias,
                                               const float* __restrict__ feature,
                                               float* __restrict__ out) {
    extern __shared__ float sm[];
    float* sagg  = sm + SAGG_OFF;
    float* sperm = sm + PERM_OFF;
    float* sws   = sm + WS_OFF;
    float* scen  = sm + SCEN_OFF;
    float* skern = sm + SKERN_OFF;
    int*   sidx  = (int*)(sm + SIDX_OFF);

    int tid = threadIdx.x;
    int p0  = blockIdx.x * PTS;
    int b   = p0 >> 12;                       // batch (tile never crosses batch)
    const float* xb  = x + (size_t)b * 3 * N_;
    const float* ftb = g_ft + ((size_t)b * N_) * C_;

    // ---- Phase 1: indices, kernels, centers ----
    if (tid < 3 * M_) skern[tid] = kern[tid];
#pragma unroll
    for (int u = tid; u < PTS * K_; u += TPB) sidx[u] = nbr[(size_t)p0 * K_ + u];
    __syncthreads();
    if (tid < PTS) {
        int c0i = sidx[tid * K_];             // neighbor 0 = softmax anchor
        scen[tid * 4 + 0] = xb[c0i];
        scen[tid * 4 + 1] = xb[N_ + c0i];
        scen[tid * 4 + 2] = xb[2 * N_ + c0i];
    }
    __syncthreads();

    // ---- Phase 2: perm logits (1280 (p,k) pairs, 5 per thread) ----
#pragma unroll
    for (int u = tid; u < PTS * K_; u += TPB) {
        int p = u / K_;
        int k = u - p * K_;
        int ii = sidx[u];
        float r0 = xb[ii]          - scen[p * 4 + 0];
        float r1 = xb[N_ + ii]     - scen[p * 4 + 1];
        float r2 = xb[2 * N_ + ii] - scen[p * 4 + 2];
        float* pr = sperm + p * 180 + k * 9;
#pragma unroll
        for (int m = 0; m < M_; m++) {
            float v = r0 * skern[m] + r1 * skern[M_ + m] + r2 * skern[2 * M_ + m];
            if (k == 0 && m == 0) v += 1.0f;
            pr[m] = v;
        }
    }
    __syncthreads();

    // ---- Phase 3: softmax over k for each (p, m) (512 tasks, 2 per thread) ----
#pragma unroll
    for (int u = tid; u < PTS * M_; u += TPB) {
        int p = u >> 3;
        int m = u & 7;
        float* col = sperm + p * 180 + m;
        float mx = -1e30f;
#pragma unroll
        for (int k = 0; k < K_; k++) mx = fmaxf(mx, col[k * 9]);
        float s = 0.0f;
#pragma unroll
        for (int k = 0; k < K_; k++) {
            float e = __expf(col[k * 9] - mx);
            col[k * 9] = e;
            s += e;
        }
        float inv = 1.0f / s;
#pragma unroll
        for (int k = 0; k < K_; k++) col[k * 9] *= inv;
    }
    __syncthreads();

    // ---- Phase 4: aggregation (4096 (p,c) pairs, 16 per thread) ----
#pragma unroll
    for (int u = tid; u < PTS * C_; u += TPB) {
        int p = u >> 6;
        int c = u & 63;                        // warp = 32 consecutive c -> coalesced
        const float* pr = sperm + p * 180;
        float acc[M_];
#pragma unroll
        for (int m = 0; m < M_; m++) acc[m] = 0.0f;
#pragma unroll
        for (int k = 0; k < K_; k++) {
            float f = ftb[(size_t)sidx[p * K_ + k] * C_ + c];
            const float* pk = pr + k * 9;      // broadcast within warp (same p)
#pragma unroll
            for (int m = 0; m < M_; m++) acc[m] = fmaf(f, pk[m], acc[m]);
        }
        // scalar stores: row stride 513 words means float4 would be misaligned
        float* ap = sagg + p * 513 + c * M_;
#pragma unroll
        for (int m = 0; m < M_; m++) ap[m] = acc[m];
    }
    __syncthreads();

    // ---- Phase 5: GEMM 64x64x512 from smem + epilogue ----
    int tx = tid & 15;                         // p  = tx + 16*i  (i<4)
    int ty = tid >> 4;                         // oc = ty + 16*j  (j<4)

    float acc[4][4];
#pragma unroll
    for (int i = 0; i < 4; i++)
#pragma unroll
        for (int j = 0; j < 4; j++) acc[i][j] = 0.0f;

    for (int k0 = 0; k0 < CM; k0 += 32) {
        // stage W chunk: 64 oc x 32 k  (512 float4 units, 2 per thread)
#pragma unroll
        for (int r = 0; r < 2; r++) {
            int u  = r * 256 + tid;
            int oc = u >> 3;
            int kq = u & 7;
            float4 v = *(const float4*)(w + (size_t)oc * CM + k0 + kq * 4);
            sws[(kq * 4 + 0) * 65 + oc] = v.x;
            sws[(kq * 4 + 1) * 65 + oc] = v.y;
            sws[(kq * 4 + 2) * 65 + oc] = v.z;
            sws[(kq * 4 + 3) * 65 + oc] = v.w;
        }
        __syncthreads();

#pragma unroll
        for (int kk = 0; kk < 32; kk++) {
            float a[4], wv[4];
#pragma unroll
            for (int i = 0; i < 4; i++) a[i]  = sagg[(tx + 16 * i) * 513 + k0 + kk];
#pragma unroll
            for (int j = 0; j < 4; j++) wv[j] = sws[kk * 65 + ty + 16 * j];
#pragma unroll
            for (int i = 0; i < 4; i++)
#pragma unroll
                for (int j = 0; j < 4; j++)
                    acc[i][j] = fmaf(a[i], wv[j], acc[i][j]);
        }
        __syncthreads();
    }

    // epilogue: bias + leaky_relu + residual, store (B,OUTC,N)
    int nb = (p0 & (N_ - 1)) + tx;
#pragma unroll
    for (int j = 0; j < 4; j++) {
        int oc   = ty + 16 * j;
        float bi = bias[oc];
        const float* fptr = feature + ((size_t)b * C_ + oc) * N_;
        float*       optr = out     + ((size_t)b * OUTC + oc) * N_;
#pragma unroll
        for (int i = 0; i < 4; i++) {
            int n = nb + 16 * i;
            float tv = acc[i][j] + bi;
            tv = tv > 0.0f ? tv : NEG_SLOPE * tv;
            optr[n] = tv + fptr[n];
        }
    }
}

// ---------------------------------------------------------------------------
// Launch
// ---------------------------------------------------------------------------
extern "C" void kernel_launch(void* const* d_in, const int* in_sizes, int n_in,
                              void* d_out, int out_size) {
    const float* x      = (const float*)d_in[0];       // (B,3,N)
    const float* feat   = (const float*)d_in[1];       // (B,C,N)
    const int*   nbr    = (const int*)d_in[2];         // (B,N,K) int32 on device
    const float* kern   = (const float*)d_in[3];       // (3,M)
    const float* conv_w = (const float*)d_in[4];       // (OUTC, C*M)
    const float* conv_b = (const float*)d_in[5];       // (OUTC,)
    float*       out    = (float*)d_out;               // (B,OUTC,N)

    // K1: transpose feature -> g_ft
    dim3 tb(32, 8);
    dim3 tg(N_ / 32, C_ / 32, B_);
    k_transpose<<<tg, tb>>>(feat);

    // K2: fused perm/softmax/agg/GEMM/epilogue
    static bool smem_set = false;
    int smem_bytes = SMEM_WORDS * 4;                   // 192000 B
    if (!smem_set) {
        cudaFuncSetAttribute(k_fused, cudaFuncAttributeMaxDynamicSharedMemorySize,
                             smem_bytes);
        smem_set = true;
    }
    k_fused<<<P_ / PTS, TPB, smem_bytes>>>(x, nbr, kern, conv_w, conv_b, feat, out);
}

// round 14
// speedup vs baseline: 1.3644x; 1.3644x over previous
#include <cuda_runtime.h>
#include <cuda_bf16.h>
#include <cstdint>

// Problem constants
#define B_   8
#define C_   64
#define N_   4096
#define K_   20
#define M_   8
#define OUTC 64
#define CM   (C_ * M_)      // 512
#define P_   (B_ * N_)      // 32768 points
#define NEG_SLOPE 0.2f

typedef unsigned long long ull;

// Packed fp32x2 FMA (sm_100+): d = a*b + c per 32-bit half, bit-exact vs fmaf.
#define FFMA2(d, a, b, c) \
    asm("fma.rn.f32x2 %0, %1, %2, %3;" : "=l"(d) : "l"(a), "l"(b), "l"(c))
#define PACK2(d, lo, hi) \
    asm("mov.b64 %0, {%1, %2};" : "=l"(d) : "f"(lo), "f"(hi))
#define UNPACK2(lo, hi, s) \
    asm("mov.b64 {%0, %1}, %2;" : "=f"(lo), "=f"(hi) : "l"(s))

// Scratch (allocation-free: __device__ globals)
__device__ float g_ft[(size_t)B_ * N_ * C_];        // feature transposed (B,N,C)  8 MB
__device__ float g_agg[(size_t)P_ * CM];            // per-point agg vectors       64 MB

// ---------------------------------------------------------------------------
// Kernel 1: transpose feature (B,C,N) -> ft (B,N,C)
// ---------------------------------------------------------------------------
__global__ void k_transpose(const float* __restrict__ feature) {
    __shared__ float tile[32][33];
    int b  = blockIdx.z;
    int c0 = blockIdx.y * 32;
    int n0 = blockIdx.x * 32;
    int tx = threadIdx.x;
    int ty = threadIdx.y;

    const float* src = feature + ((size_t)b * C_) * N_;
#pragma unroll
    for (int i = 0; i < 32; i += 8) {
        tile[ty + i][tx] = src[(size_t)(c0 + ty + i) * N_ + (n0 + tx)];
    }
    __syncthreads();
    float* dst = g_ft + ((size_t)b * N_) * C_;
#pragma unroll
    for (int i = 0; i < 32; i += 8) {
        dst[(size_t)(n0 + ty + i) * C_ + (c0 + tx)] = tile[tx][ty + i];
    }
}

// ---------------------------------------------------------------------------
// Kernel 2: per-point perm matrix + softmax + feature aggregation.
// 128 threads per block, 2 points per block.  FFMA2 over the m dimension.
// ---------------------------------------------------------------------------
__global__ __launch_bounds__(128) void k_agg(const float* __restrict__ x,
                                             const int* __restrict__ nbr,
                                             const float* __restrict__ kern) {
    int t  = threadIdx.x;          // 0..127
    int q  = t >> 6;               // local point 0/1
    int tq = t & 63;               // lane within point group
    int p  = blockIdx.x * 2 + q;   // global point
    int b  = p >> 12;              // / 4096

    __shared__ __align__(16) float perm[2][K_][M_];   // 8B-aligned pairs
    __shared__ float px[2][K_][3];
    __shared__ int   sidx[2][K_];
    __shared__ float skern[3 * M_];

    if (t < 3 * M_) skern[t] = kern[t];
    if (tq < K_) {
        int ii = nbr[(size_t)p * K_ + tq];
        sidx[q][tq] = ii;
        const float* xb = x + (size_t)b * 3 * N_;
        px[q][tq][0] = xb[ii];
        px[q][tq][1] = xb[N_ + ii];
        px[q][tq][2] = xb[2 * N_ + ii];
    }
    __syncthreads();

    if (tq < K_) {
        float r0 = px[q][tq][0] - px[q][0][0];
        float r1 = px[q][tq][1] - px[q][0][1];
        float r2 = px[q][tq][2] - px[q][0][2];
#pragma unroll
        for (int m = 0; m < M_; m++) {
            float v = r0 * skern[m] + r1 * skern[M_ + m] + r2 * skern[2 * M_ + m];
            if (tq == 0 && m == 0) v += 1.0f;
            perm[q][tq][m] = v;
        }
    }
    __syncthreads();

    // softmax over k (axis 2) for each column m
    if (tq < M_) {
        float mx = -1e30f;
#pragma unroll
        for (int k = 0; k < K_; k++) mx = fmaxf(mx, perm[q][k][tq]);
        float s = 0.0f;
#pragma unroll
        for (int k = 0; k < K_; k++) {
            float e = __expf(perm[q][k][tq] - mx);
            perm[q][k][tq] = e;
            s += e;
        }
        float inv = 1.0f / s;
#pragma unroll
        for (int k = 0; k < K_; k++) perm[q][k][tq] *= inv;
    }
    __syncthreads();

    // tq == channel c ; gather 20 neighbor features, accumulate agg[c][m]
    // FFMA2: acc pairs over m.
    ull acc2[4];
#pragma unroll
    for (int h = 0; h < 4; h++) acc2[h] = 0ull;   // {+0.f, +0.f}

    const float* ftb = g_ft + ((size_t)b * N_) * C_;
#pragma unroll
    for (int k = 0; k < K_; k++) {
        float f = ftb[(size_t)sidx[q][k] * C_ + tq];
        ull fd; PACK2(fd, f, f);
        const ull* pk = (const ull*)&perm[q][k][0];   // 4 pairs, 8B-aligned
#pragma unroll
        for (int h = 0; h < 4; h++) FFMA2(acc2[h], fd, pk[h], acc2[h]);
    }

    float a[M_];
#pragma unroll
    for (int h = 0; h < 4; h++) UNPACK2(a[2 * h], a[2 * h + 1], acc2[h]);

    float* outp = g_agg + (size_t)p * CM + tq * M_;
    *(float4*)(outp)     = make_float4(a[0], a[1], a[2], a[3]);
    *(float4*)(outp + 4) = make_float4(a[4], a[5], a[6], a[7]);
}

// ---------------------------------------------------------------------------
// Kernel 3: GEMM  out[p][oc] = sum_j agg[p][j] * W[oc][j]  + epilogue
//   BM=128 points per block, all 64 oc, BK=32.  256 threads.
//   FFMA2 micro-kernel: 4 point-pairs x 4 oc per thread (8x4 scalar tile).
//   Point pairs: p_local = tx*2 + 32*pi + half  (tx<16, pi<4, half<2)
//   As stride 130 (even) -> LDS.64 pair loads stay 8B-aligned for all kk.
//   Epilogue: + bias, leaky_relu(0.2), + feature residual, store (B,OUTC,N)
// ---------------------------------------------------------------------------
#define BM 128
#define BK 32
#define BMP (BM + 2)     // 130: even stride, conflict-free pair reads

__global__ __launch_bounds__(256) void k_gemm(const float* __restrict__ w,
                                              const float* __restrict__ bias,
                                              const float* __restrict__ feature,
                                              float* __restrict__ out) {
    int p0  = blockIdx.x * BM;
    int tid = threadIdx.x;
    int tx  = tid & 15;            // point-pair group
    int ty  = tid >> 4;            // oc group: oc = ty + 16*j

    __shared__ __align__(16) float As[BK][BMP];   // k-major
    __shared__ float Ws[BK][OUTC + 1];

    ull acc2[4][4];
#pragma unroll
    for (int i = 0; i < 4; i++)
#pragma unroll
        for (int j = 0; j < 4; j++) acc2[i][j] = 0ull;

    for (int k0 = 0; k0 < CM; k0 += BK) {
        // Stage A: 128 rows (points) x 32 k as float4 units (4 per thread).
#pragma unroll
        for (int r = 0; r < 4; r++) {
            int u   = r * 256 + tid;
            int row = u >> 3;            // 0..127
            int kq  = u & 7;             // k-quad 0..7
            float4 v = *(const float4*)(g_agg + (size_t)(p0 + row) * CM + k0 + kq * 4);
            As[kq * 4 + 0][row] = v.x;
            As[kq * 4 + 1][row] = v.y;
            As[kq * 4 + 2][row] = v.z;
            As[kq * 4 + 3][row] = v.w;
        }
        // Stage W: 64 rows (oc) x 32 k as float4 units (2 per thread).
#pragma unroll
        for (int r = 0; r < 2; r++) {
            int u  = r * 256 + tid;
            int oc = u >> 3;             // 0..63
            int kq = u & 7;
            float4 v = *(const float4*)(w + (size_t)oc * CM + k0 + kq * 4);
            Ws[kq * 4 + 0][oc] = v.x;
            Ws[kq * 4 + 1][oc] = v.y;
            Ws[kq * 4 + 2][oc] = v.z;
            Ws[kq * 4 + 3][oc] = v.w;
        }
        __syncthreads();

#pragma unroll
        for (int kk = 0; kk < BK; kk++) {
            // 4 point-pairs: addresses kk*130 + tx*2 + 32*pi (all even words)
            const float* arow = &As[kk][0];
            ull a2[4];
#pragma unroll
            for (int i = 0; i < 4; i++)
                a2[i] = *(const ull*)(arow + tx * 2 + 32 * i);
            ull wd[4];
#pragma unroll
            for (int j = 0; j < 4; j++) {
                float wv = Ws[kk][ty + 16 * j];
                PACK2(wd[j], wv, wv);
            }
#pragma unroll
            for (int i = 0; i < 4; i++)
#pragma unroll
                for (int j = 0; j < 4; j++)
                    FFMA2(acc2[i][j], a2[i], wd[j], acc2[i][j]);
        }
        __syncthreads();
    }

    // Epilogue.  128-point tile never crosses a batch boundary.
    int b   = p0 >> 12;
    int nb0 = (p0 & (N_ - 1));
#pragma unroll
    for (int j = 0; j < 4; j++) {
        int oc   = ty + 16 * j;
        float bi = bias[oc];
        const float* fptr = feature + ((size_t)b * C_ + oc) * N_;
        float*       optr = out     + ((size_t)b * OUTC + oc) * N_;
#pragma unroll
        for (int i = 0; i < 4; i++) {
            float v0, v1;
            UNPACK2(v0, v1, acc2[i][j]);
            int n0i = nb0 + tx * 2 + 32 * i;
            float t0 = v0 + bi;
            t0 = t0 > 0.0f ? t0 : NEG_SLOPE * t0;
            optr[n0i] = t0 + fptr[n0i];
            float t1 = v1 + bi;
            t1 = t1 > 0.0f ? t1 : NEG_SLOPE * t1;
            optr[n0i + 1] = t1 + fptr[n0i + 1];
        }
    }
}

// ---------------------------------------------------------------------------
// Launch
// ---------------------------------------------------------------------------
extern "C" void kernel_launch(void* const* d_in, const int* in_sizes, int n_in,
                              void* d_out, int out_size) {
    const float* x      = (const float*)d_in[0];       // (B,3,N)
    const float* feat   = (const float*)d_in[1];       // (B,C,N)
    const int*   nbr    = (const int*)d_in[2];         // (B,N,K) int32 on device
    const float* kern   = (const float*)d_in[3];       // (3,M)
    const float* conv_w = (const float*)d_in[4];       // (OUTC, C*M)
    const float* conv_b = (const float*)d_in[5];       // (OUTC,)
    float*       out    = (float*)d_out;               // (B,OUTC,N)

    // K1: transpose feature -> g_ft
    dim3 tb(32, 8);
    dim3 tg(N_ / 32, C_ / 32, B_);
    k_transpose<<<tg, tb>>>(feat);

    // K2: per-point aggregation -> g_agg   (2 points / block)
    k_agg<<<P_ / 2, 128>>>(x, nbr, kern);

    // K3: GEMM + epilogue -> out
    k_gemm<<<P_ / BM, 256>>>(conv_w, conv_b, feat, out);
}